// round 2
// baseline (speedup 1.0000x reference)
#include <cuda_runtime.h>

// Problem constants (match reference_code)
#define N_ATOMS   100000
#define N_BONDS   200000
#define MAX_NB    6
#define ATOM_FDIM 133
#define BOND_FDIM 147
#define HIDDEN    300
#define N_MOLS_C  5000

// ---------------------------------------------------------------------------
// Scratch (device globals — no allocation allowed). Referenced directly from
// device code; kernel_launch performs ONLY kernel launches (graph-capture safe).
// ---------------------------------------------------------------------------
__device__ float g_inp [(size_t)N_BONDS * HIDDEN];  // f_bonds @ W_i (pre-relu)
__device__ float g_msg [(size_t)N_BONDS * HIDDEN];  // current message (post-relu)
__device__ float g_min [(size_t)N_BONDS * HIDDEN];  // bond GEMM input
__device__ float g_amsg[(size_t)N_ATOMS * HIDDEN];  // per-atom summed messages
__device__ float g_hid [(size_t)N_ATOMS * HIDDEN];  // atom hiddens

// ---------------------------------------------------------------------------
// SGEMM: BM=128 BN=64 BK=8, 256 threads, 8x4 per-thread tile.
// MODE 0: C = A@B            -> g_inp (raw), g_msg = relu
// MODE 1: C = relu(g_inp + g_min@B)            -> g_msg
// MODE 2: C = A@B            -> g_hid (raw)
// MODE 3: C = relu(g_hid + g_amsg@B + bias)    -> g_hid
// ---------------------------------------------------------------------------
#define BM 128
#define BN 64
#define BK 8
#define TM 8
#define TN 4

template <int MODE>
__global__ __launch_bounds__(256)
void sgemm_kernel(const float* __restrict__ Aext, const float* __restrict__ B,
                  const float* __restrict__ bias, int M, int K)
{
    const float* A;
    if (MODE == 1)      A = g_min;
    else if (MODE == 3) A = g_amsg;
    else                A = Aext;

    __shared__ float As[BK][BM + 4];
    __shared__ float Bs[BK][BN];

    const int tid  = threadIdx.x;
    const int row0 = blockIdx.y * BM;
    const int col0 = blockIdx.x * BN;
    const int tx = tid & 15;           // cols tx*TN
    const int ty = tid >> 4;           // rows ty*TM

    const int ak = tid & 7;
    const int am = tid >> 3;           // 0..31, +32*i
    const int bn = tid & 63;
    const int bk = tid >> 6;           // 0..3, +4*i

    float acc[TM][TN];
#pragma unroll
    for (int i = 0; i < TM; i++)
#pragma unroll
        for (int j = 0; j < TN; j++) acc[i][j] = 0.f;

    for (int k0 = 0; k0 < K; k0 += BK) {
#pragma unroll
        for (int i = 0; i < 4; i++) {
            int m  = am + 32 * i;
            int gm = row0 + m;
            int gk = k0 + ak;
            As[ak][m] = (gm < M && gk < K) ? A[(size_t)gm * K + gk] : 0.f;
        }
#pragma unroll
        for (int i = 0; i < 2; i++) {
            int kk = bk + 4 * i;
            int gk = k0 + kk;
            int gn = col0 + bn;
            Bs[kk][bn] = (gk < K && gn < HIDDEN) ? B[(size_t)gk * HIDDEN + gn] : 0.f;
        }
        __syncthreads();

#pragma unroll
        for (int k = 0; k < BK; k++) {
            float a[TM], b[TN];
#pragma unroll
            for (int i = 0; i < TM; i++) a[i] = As[k][ty * TM + i];
#pragma unroll
            for (int j = 0; j < TN; j++) b[j] = Bs[k][tx * TN + j];
#pragma unroll
            for (int i = 0; i < TM; i++)
#pragma unroll
                for (int j = 0; j < TN; j++)
                    acc[i][j] += a[i] * b[j];
        }
        __syncthreads();
    }

#pragma unroll
    for (int i = 0; i < TM; i++) {
        int r = row0 + ty * TM + i;
        if (r >= M) continue;
#pragma unroll
        for (int j = 0; j < TN; j++) {
            int c = col0 + tx * TN + j;
            if (c >= HIDDEN) continue;
            size_t idx = (size_t)r * HIDDEN + c;
            float v = acc[i][j];
            if (MODE == 0) {
                g_inp[idx] = v;
                g_msg[idx] = fmaxf(v, 0.f);
            } else if (MODE == 1) {
                g_msg[idx] = fmaxf(v + g_inp[idx], 0.f);
            } else if (MODE == 2) {
                g_hid[idx] = v;
            } else { // MODE 3
                g_hid[idx] = fmaxf(v + g_hid[idx] + bias[c], 0.f);
            }
        }
    }
}

// ---------------------------------------------------------------------------
// g_amsg[a,:] = sum_{k<6} g_msg[a2b[a,k], :]
// ---------------------------------------------------------------------------
__global__ __launch_bounds__(128)
void atom_gather_kernel(const int* __restrict__ a2b)
{
    const int a = blockIdx.x;
    int b[MAX_NB];
#pragma unroll
    for (int k = 0; k < MAX_NB; k++) b[k] = a2b[a * MAX_NB + k];
    for (int c = threadIdx.x; c < HIDDEN; c += 128) {
        float s = 0.f;
#pragma unroll
        for (int k = 0; k < MAX_NB; k++) s += g_msg[(size_t)b[k] * HIDDEN + c];
        g_amsg[(size_t)a * HIDDEN + c] = s;
    }
}

// ---------------------------------------------------------------------------
// g_min[b,:] = g_amsg[b2a[b], :] - g_msg[b2revb[b], :]
// ---------------------------------------------------------------------------
__global__ __launch_bounds__(128)
void bond_prep_kernel(const int* __restrict__ b2a, const int* __restrict__ b2revb)
{
    const int b  = blockIdx.x;
    const int a  = b2a[b];
    const int rb = b2revb[b];
    for (int c = threadIdx.x; c < HIDDEN; c += 128)
        g_min[(size_t)b * HIDDEN + c] =
            g_amsg[(size_t)a * HIDDEN + c] - g_msg[(size_t)rb * HIDDEN + c];
}

// ---------------------------------------------------------------------------
// Per-molecule mean pool over sorted a2mol (binary search for range).
// ---------------------------------------------------------------------------
__global__ __launch_bounds__(128)
void pool_kernel(const int* __restrict__ a2mol, float* __restrict__ out)
{
    const int m = blockIdx.x;
    int lo = 0, hi = N_ATOMS;
    while (lo < hi) { int mid = (lo + hi) >> 1; if (a2mol[mid] <  m) lo = mid + 1; else hi = mid; }
    const int start = lo;
    hi = N_ATOMS;
    while (lo < hi) { int mid = (lo + hi) >> 1; if (a2mol[mid] <= m) lo = mid + 1; else hi = mid; }
    const int end = lo;
    const float inv = (end > start) ? 1.f / (float)(end - start) : 0.f;
    for (int c = threadIdx.x; c < HIDDEN; c += 128) {
        float s = 0.f;
        for (int a = start; a < end; a++) s += g_hid[(size_t)a * HIDDEN + c];
        out[(size_t)m * HIDDEN + c] = s * inv;
    }
}

// ---------------------------------------------------------------------------
// Launch (kernel launches only — graph-capture safe)
// ---------------------------------------------------------------------------
extern "C" void kernel_launch(void* const* d_in, const int* in_sizes, int n_in,
                              void* d_out, int out_size)
{
    const float* f_atoms = (const float*)d_in[0];
    const float* f_bonds = (const float*)d_in[1];
    const int*   a2b     = (const int*)  d_in[2];
    const int*   b2a     = (const int*)  d_in[3];
    const int*   b2revb  = (const int*)  d_in[4];
    const int*   a2mol   = (const int*)  d_in[5];
    int wbase = 6;
    if (n_in >= 11 && in_sizes[6] == 1) wbase = 7;   // scalar n_mols present
    const float* W_i = (const float*)d_in[wbase + 0];
    const float* W_h = (const float*)d_in[wbase + 1];
    const float* W_o = (const float*)d_in[wbase + 2];
    const float* b_o = (const float*)d_in[wbase + 3];
    float* out = (float*)d_out;

    const dim3 grid_b((HIDDEN + BN - 1) / BN, (N_BONDS + BM - 1) / BM);
    const dim3 grid_a((HIDDEN + BN - 1) / BN, (N_ATOMS + BM - 1) / BM);

    // 1) inp = f_bonds @ W_i ; msg = relu(inp)
    sgemm_kernel<0><<<grid_b, 256>>>(f_bonds, W_i, nullptr, N_BONDS, BOND_FDIM);

    // 2) message-passing iterations (DEPTH-1 = 2)
    for (int it = 0; it < 2; it++) {
        atom_gather_kernel<<<N_ATOMS, 128>>>(a2b);
        bond_prep_kernel<<<N_BONDS, 128>>>(b2a, b2revb);
        sgemm_kernel<1><<<grid_b, 256>>>(nullptr, W_h, nullptr, N_BONDS, HIDDEN);
    }

    // 3) final neighbor sum
    atom_gather_kernel<<<N_ATOMS, 128>>>(a2b);

    // 4) atom_hiddens = relu([f_atoms | a_msg] @ W_o + b_o), split over K
    sgemm_kernel<2><<<grid_a, 256>>>(f_atoms, W_o, nullptr, N_ATOMS, ATOM_FDIM);
    sgemm_kernel<3><<<grid_a, 256>>>(nullptr, W_o + (size_t)ATOM_FDIM * HIDDEN,
                                     b_o, N_ATOMS, HIDDEN);

    // 5) per-molecule mean pool
    pool_kernel<<<N_MOLS_C, 128>>>(a2mol, out);
}

// round 4
// speedup vs baseline: 1.4035x; 1.4035x over previous
#include <cuda_runtime.h>
#include <cuda_bf16.h>
#include <cstdint>

// ---------------------------------------------------------------------------
// Problem constants
// ---------------------------------------------------------------------------
#define N_ATOMS   100000
#define N_BONDS   200000
#define MAX_NB    6
#define ATOM_FDIM 133
#define BOND_FDIM 147
#define HIDDEN    300
#define N_MOLS_C  5000
#define CAT_DIM   433          // ATOM_FDIM + HIDDEN

// Padded dims
#define KP_BOND 160            // ceil(147/32)*32
#define KP_HID  320            // ceil(300/32)*32
#define KP_CAT  448            // ceil(433/32)*32
#define NPAD    320            // output cols padded (2 tiles of 160)

// GEMM tiling
#define BM 128
#define BN 160
#define BK 32
// smem: rows padded to 80 B (40 bf16) for conflict-free ldmatrix
#define A_BYTES  (128 * 80)            // 10240
#define B_BYTES  (160 * 80)            // 12800
#define OFF_ALO  A_BYTES
#define OFF_BHI  (2 * A_BYTES)
#define OFF_BLO  (2 * A_BYTES + B_BYTES)
#define STAGE    (2 * A_BYTES + 2 * B_BYTES)   // 46080
#define SMEM_GEMM (2 * STAGE)                  // 92160

// ---------------------------------------------------------------------------
// Scratch (device globals — no allocation)
// ---------------------------------------------------------------------------
__device__ float g_inp [(size_t)N_BONDS * HIDDEN];
__device__ float g_msg [(size_t)N_BONDS * HIDDEN];
__device__ float g_min [(size_t)N_BONDS * HIDDEN];
__device__ float g_amsg[(size_t)N_ATOMS * HIDDEN];
__device__ float g_cat [(size_t)N_ATOMS * CAT_DIM];
__device__ float g_hid [(size_t)N_ATOMS * HIDDEN];

__device__ __nv_bfloat16 g_Wi_hi[(size_t)NPAD * KP_BOND];
__device__ __nv_bfloat16 g_Wi_lo[(size_t)NPAD * KP_BOND];
__device__ __nv_bfloat16 g_Wh_hi[(size_t)NPAD * KP_HID];
__device__ __nv_bfloat16 g_Wh_lo[(size_t)NPAD * KP_HID];
__device__ __nv_bfloat16 g_Wo_hi[(size_t)NPAD * KP_CAT];
__device__ __nv_bfloat16 g_Wo_lo[(size_t)NPAD * KP_CAT];

// ---------------------------------------------------------------------------
// PTX helpers (sm_80-era ISA only — harness compiles for plain sm_100)
// ---------------------------------------------------------------------------
__device__ __forceinline__ uint32_t smem_u32(const void* p) {
    uint32_t a;
    asm("{ .reg .u64 t; cvta.to.shared.u64 t, %1; cvt.u32.u64 %0, t; }"
        : "=r"(a) : "l"(p));
    return a;
}
__device__ __forceinline__ void cpa16(uint32_t d, const void* s) {
    asm volatile("cp.async.cg.shared.global [%0], [%1], 16;" :: "r"(d), "l"(s));
}
#define CP_COMMIT() asm volatile("cp.async.commit_group;" ::: "memory")
#define CP_WAIT0()  asm volatile("cp.async.wait_group 0;" ::: "memory")

__device__ __forceinline__ void ldm4(uint32_t* r, uint32_t addr) {
    asm volatile("ldmatrix.sync.aligned.m8n8.x4.shared.b16 {%0,%1,%2,%3}, [%4];"
                 : "=r"(r[0]), "=r"(r[1]), "=r"(r[2]), "=r"(r[3]) : "r"(addr));
}
__device__ __forceinline__ void mma16816(float* c, const uint32_t* a,
                                         uint32_t b0, uint32_t b1) {
    asm volatile("mma.sync.aligned.m16n8k16.row.col.f32.bf16.bf16.f32 "
                 "{%0,%1,%2,%3}, {%4,%5,%6,%7}, {%8,%9}, {%0,%1,%2,%3};"
                 : "+f"(c[0]), "+f"(c[1]), "+f"(c[2]), "+f"(c[3])
                 : "r"(a[0]), "r"(a[1]), "r"(a[2]), "r"(a[3]), "r"(b0), "r"(b1));
}
__device__ __forceinline__ void split2(float v, __nv_bfloat16& h, __nv_bfloat16& l) {
    h = __float2bfloat16(v);
    l = __float2bfloat16(v - __bfloat162float(h));
}

// ---------------------------------------------------------------------------
// Weight conversion: W[k][300] fp32 -> transposed [NPAD][KP] bf16 hi/lo
// ---------------------------------------------------------------------------
template <int WS>
__global__ __launch_bounds__(256)
void conv_weight(const float* __restrict__ W)
{
    constexpr int K  = (WS == 0) ? BOND_FDIM : (WS == 1) ? HIDDEN : CAT_DIM;
    constexpr int KP = (WS == 0) ? KP_BOND   : (WS == 1) ? KP_HID : KP_CAT;
    __nv_bfloat16* H = (WS == 0) ? g_Wi_hi : (WS == 1) ? g_Wh_hi : g_Wo_hi;
    __nv_bfloat16* L = (WS == 0) ? g_Wi_lo : (WS == 1) ? g_Wh_lo : g_Wo_lo;
    int idx = blockIdx.x * 256 + threadIdx.x;
    if (idx >= NPAD * KP) return;
    int n = idx / KP, k = idx % KP;
    float v = (n < HIDDEN && k < K) ? W[(size_t)k * HIDDEN + n] : 0.f;
    __nv_bfloat16 h, l; split2(v, h, l);
    H[idx] = h; L[idx] = l;
}

// copy f_atoms into g_cat cols [0,133)
__global__ __launch_bounds__(256)
void copy_atoms(const float* __restrict__ fa)
{
    int idx = blockIdx.x * 256 + threadIdx.x;
    if (idx >= N_ATOMS * ATOM_FDIM) return;
    int a = idx / ATOM_FDIM, k = idx % ATOM_FDIM;
    g_cat[(size_t)a * CAT_DIM + k] = fa[idx];
}

// ---------------------------------------------------------------------------
// Gathers (fp32)
// ---------------------------------------------------------------------------
__global__ __launch_bounds__(96)
void atom_gather(const int* __restrict__ a2b)
{
    int a = blockIdx.x, t = threadIdx.x;
    if (t >= 75) return;
    const float4* m4 = (const float4*)g_msg;
    int b0 = a2b[a*MAX_NB+0], b1 = a2b[a*MAX_NB+1], b2 = a2b[a*MAX_NB+2];
    int b3 = a2b[a*MAX_NB+3], b4 = a2b[a*MAX_NB+4], b5 = a2b[a*MAX_NB+5];
    float4 s  = m4[(size_t)b0*75 + t];
    float4 v1 = m4[(size_t)b1*75 + t]; float4 v2 = m4[(size_t)b2*75 + t];
    float4 v3 = m4[(size_t)b3*75 + t]; float4 v4 = m4[(size_t)b4*75 + t];
    float4 v5 = m4[(size_t)b5*75 + t];
    s.x += v1.x+v2.x+v3.x+v4.x+v5.x;  s.y += v1.y+v2.y+v3.y+v4.y+v5.y;
    s.z += v1.z+v2.z+v3.z+v4.z+v5.z;  s.w += v1.w+v2.w+v3.w+v4.w+v5.w;
    ((float4*)g_amsg)[(size_t)a*75 + t] = s;
}

__global__ __launch_bounds__(96)
void atom_gather_cat(const int* __restrict__ a2b)   // into g_cat cols 133..432
{
    int a = blockIdx.x, t = threadIdx.x;
    if (t >= 75) return;
    const float4* m4 = (const float4*)g_msg;
    int b0 = a2b[a*MAX_NB+0], b1 = a2b[a*MAX_NB+1], b2 = a2b[a*MAX_NB+2];
    int b3 = a2b[a*MAX_NB+3], b4 = a2b[a*MAX_NB+4], b5 = a2b[a*MAX_NB+5];
    float4 s  = m4[(size_t)b0*75 + t];
    float4 v1 = m4[(size_t)b1*75 + t]; float4 v2 = m4[(size_t)b2*75 + t];
    float4 v3 = m4[(size_t)b3*75 + t]; float4 v4 = m4[(size_t)b4*75 + t];
    float4 v5 = m4[(size_t)b5*75 + t];
    float c[4];
    c[0] = s.x+v1.x+v2.x+v3.x+v4.x+v5.x;  c[1] = s.y+v1.y+v2.y+v3.y+v4.y+v5.y;
    c[2] = s.z+v1.z+v2.z+v3.z+v4.z+v5.z;  c[3] = s.w+v1.w+v2.w+v3.w+v4.w+v5.w;
    size_t base = (size_t)a * CAT_DIM + ATOM_FDIM + 4*t;
#pragma unroll
    for (int i = 0; i < 4; i++) g_cat[base + i] = c[i];
}

__global__ __launch_bounds__(96)
void bond_prep(const int* __restrict__ b2a, const int* __restrict__ b2revb)
{
    int b = blockIdx.x, t = threadIdx.x;
    if (t >= 75) return;
    int a = b2a[b], rb = b2revb[b];
    float4 x = ((const float4*)g_amsg)[(size_t)a*75 + t];
    float4 y = ((const float4*)g_msg)[(size_t)rb*75 + t];
    float4 o = {x.x-y.x, x.y-y.y, x.z-y.z, x.w-y.w};
    ((float4*)g_min)[(size_t)b*75 + t] = o;
}

// ---------------------------------------------------------------------------
// bf16x3 split-float GEMM via mma.sync.
// MODE 0: C = f_bonds @ W_i  -> g_inp raw, g_msg relu     (KA=147)
// MODE 1: C = g_min  @ W_h   -> g_msg = relu(C + g_inp)   (KA=300)
// MODE 2: C = g_cat  @ W_o   -> g_hid = relu(C + bias)    (KA=433)
// ---------------------------------------------------------------------------
template <int MODE>
__global__ __launch_bounds__(256)
void mma_gemm(const float* __restrict__ Aext, const float* __restrict__ bias)
{
    constexpr int KA = (MODE == 0) ? BOND_FDIM : (MODE == 1) ? HIDDEN : CAT_DIM;
    constexpr int KP = (MODE == 0) ? KP_BOND   : (MODE == 1) ? KP_HID : KP_CAT;
    constexpr int M  = (MODE == 2) ? N_ATOMS : N_BONDS;
    constexpr int NC = KP / BK;

    const float* A = (MODE == 1) ? g_min : (MODE == 2) ? g_cat : Aext;
    const __nv_bfloat16* Bh = (MODE == 0) ? g_Wi_hi : (MODE == 1) ? g_Wh_hi : g_Wo_hi;
    const __nv_bfloat16* Bl = (MODE == 0) ? g_Wi_lo : (MODE == 1) ? g_Wh_lo : g_Wo_lo;

    extern __shared__ __align__(128) char smem[];
    const uint32_t sb = smem_u32(smem);
    const int tid = threadIdx.x, lane = tid & 31, wid = tid >> 5;
    const int wm = wid & 3, wn = wid >> 2;
    const int m0 = blockIdx.y * BM, n0 = blockIdx.x * BN;

    float acc[2][10][4];
#pragma unroll
    for (int i = 0; i < 2; i++)
#pragma unroll
        for (int j = 0; j < 10; j++)
#pragma unroll
            for (int k = 0; k < 4; k++) acc[i][j][k] = 0.f;

    float areg[16];

#define LOAD_A(cc) do { \
    int _c = (cc); \
    _Pragma("unroll") \
    for (int i = 0; i < 16; i++) { \
        int idx = i * 256 + tid; \
        int row = idx >> 5, col = idx & 31; \
        int gm = m0 + row, gk = _c * BK + col; \
        areg[i] = (gm < M && gk < KA) ? A[(size_t)gm * KA + gk] : 0.f; \
    } } while (0)

#define STS_A(cc) do { \
    char* st = smem + ((cc) & 1) * STAGE; \
    _Pragma("unroll") \
    for (int i = 0; i < 16; i++) { \
        int idx = i * 256 + tid; \
        int row = idx >> 5, col = idx & 31; \
        __nv_bfloat16 h, l; split2(areg[i], h, l); \
        *(__nv_bfloat16*)(st + row * 80 + col * 2) = h; \
        *(__nv_bfloat16*)(st + OFF_ALO + row * 80 + col * 2) = l; \
    } } while (0)

#define LOAD_B(cc) do { \
    int _c = (cc); \
    uint32_t dh = sb + (_c & 1) * STAGE + OFF_BHI; \
    uint32_t dl = sb + (_c & 1) * STAGE + OFF_BLO; \
    _Pragma("unroll") \
    for (int i = 0; i < 3; i++) { \
        int idx = i * 256 + tid; \
        if (idx < 640) { \
            int row = idx >> 2, ch = idx & 3; \
            size_t g = (size_t)(n0 + row) * KP + _c * BK + ch * 8; \
            cpa16(dh + row * 80 + ch * 16, Bh + g); \
            cpa16(dl + row * 80 + ch * 16, Bl + g); \
        } \
    } } while (0)

    // prologue: stage chunk 0
    LOAD_A(0); LOAD_B(0); CP_COMMIT(); STS_A(0); CP_WAIT0(); __syncthreads();

    for (int c = 0; c < NC; c++) {
        const bool has_next = (c + 1 < NC);
        if (has_next) { LOAD_A(c + 1); LOAD_B(c + 1); CP_COMMIT(); }

        // compute chunk c from buffer c&1
        const uint32_t sA = sb + (c & 1) * STAGE;
#pragma unroll
        for (int ks = 0; ks < 2; ks++) {
            uint32_t ah[2][4], al[2][4];
#pragma unroll
            for (int mi = 0; mi < 2; mi++) {
                int row = wm * 32 + mi * 16 + (lane & 15);
                uint32_t ad = sA + row * 80 + ks * 32 + (lane >> 4) * 16;
                ldm4(ah[mi], ad);
                ldm4(al[mi], ad + OFF_ALO);
            }
            uint32_t bh[5][4], bl[5][4];
            {
                int g = lane >> 3, w = lane & 7;
                int rofs = ((g & 2) ? 8 : 0) + w;
                int cofs = ks * 32 + (g & 1) * 16;
#pragma unroll
                for (int nj = 0; nj < 5; nj++) {
                    int row = wn * 80 + nj * 16 + rofs;
                    uint32_t bd = sA + OFF_BHI + row * 80 + cofs;
                    ldm4(bh[nj], bd);
                    ldm4(bl[nj], bd + (OFF_BLO - OFF_BHI));
                }
            }
#pragma unroll
            for (int mi = 0; mi < 2; mi++)
#pragma unroll
                for (int nj = 0; nj < 5; nj++) {
                    mma16816(acc[mi][2*nj],   ah[mi], bh[nj][0], bh[nj][1]);
                    mma16816(acc[mi][2*nj],   ah[mi], bl[nj][0], bl[nj][1]);
                    mma16816(acc[mi][2*nj],   al[mi], bh[nj][0], bh[nj][1]);
                    mma16816(acc[mi][2*nj+1], ah[mi], bh[nj][2], bh[nj][3]);
                    mma16816(acc[mi][2*nj+1], ah[mi], bl[nj][2], bl[nj][3]);
                    mma16816(acc[mi][2*nj+1], al[mi], bh[nj][2], bh[nj][3]);
                }
        }

        if (has_next) { STS_A(c + 1); CP_WAIT0(); __syncthreads(); }
    }

    // epilogue: regs -> gmem, fused per MODE
    const int r_base = m0 + wm * 32 + (lane >> 2);
    const int c_base = n0 + wn * 80 + (lane & 3) * 2;
#pragma unroll
    for (int mi = 0; mi < 2; mi++)
#pragma unroll
        for (int nf = 0; nf < 10; nf++) {
            int gc = c_base + nf * 8;
#pragma unroll
            for (int h = 0; h < 2; h++) {
                int r = r_base + mi * 16 + h * 8;
                if (r >= M) continue;
#pragma unroll
                for (int q = 0; q < 2; q++) {
                    int cc = gc + q;
                    if (cc >= HIDDEN) continue;
                    float v = acc[mi][nf][h * 2 + q];
                    size_t o = (size_t)r * HIDDEN + cc;
                    if (MODE == 0)      { g_inp[o] = v; g_msg[o] = fmaxf(v, 0.f); }
                    else if (MODE == 1) { g_msg[o] = fmaxf(v + g_inp[o], 0.f); }
                    else                { g_hid[o] = fmaxf(v + bias[cc], 0.f); }
                }
            }
        }
#undef LOAD_A
#undef STS_A
#undef LOAD_B
}

// ---------------------------------------------------------------------------
// Mean pool per molecule (a2mol sorted)
// ---------------------------------------------------------------------------
__global__ __launch_bounds__(128)
void pool_kernel(const int* __restrict__ a2mol, float* __restrict__ out)
{
    const int m = blockIdx.x;
    int lo = 0, hi = N_ATOMS;
    while (lo < hi) { int mid = (lo + hi) >> 1; if (a2mol[mid] <  m) lo = mid + 1; else hi = mid; }
    const int start = lo;
    hi = N_ATOMS;
    while (lo < hi) { int mid = (lo + hi) >> 1; if (a2mol[mid] <= m) lo = mid + 1; else hi = mid; }
    const int end = lo;
    const float inv = (end > start) ? 1.f / (float)(end - start) : 0.f;
    for (int c = threadIdx.x; c < HIDDEN; c += 128) {
        float s = 0.f;
        for (int a = start; a < end; a++) s += g_hid[(size_t)a * HIDDEN + c];
        out[(size_t)m * HIDDEN + c] = s * inv;
    }
}

// ---------------------------------------------------------------------------
// Launch (kernel launches + attribute sets only — graph-capture safe)
// ---------------------------------------------------------------------------
extern "C" void kernel_launch(void* const* d_in, const int* in_sizes, int n_in,
                              void* d_out, int out_size)
{
    const float* f_atoms = (const float*)d_in[0];
    const float* f_bonds = (const float*)d_in[1];
    const int*   a2b     = (const int*)  d_in[2];
    const int*   b2a     = (const int*)  d_in[3];
    const int*   b2revb  = (const int*)  d_in[4];
    const int*   a2mol   = (const int*)  d_in[5];
    int wbase = 6;
    if (n_in >= 11 && in_sizes[6] == 1) wbase = 7;
    const float* W_i = (const float*)d_in[wbase + 0];
    const float* W_h = (const float*)d_in[wbase + 1];
    const float* W_o = (const float*)d_in[wbase + 2];
    const float* b_o = (const float*)d_in[wbase + 3];
    float* out = (float*)d_out;

    cudaFuncSetAttribute(mma_gemm<0>, cudaFuncAttributeMaxDynamicSharedMemorySize, SMEM_GEMM);
    cudaFuncSetAttribute(mma_gemm<1>, cudaFuncAttributeMaxDynamicSharedMemorySize, SMEM_GEMM);
    cudaFuncSetAttribute(mma_gemm<2>, cudaFuncAttributeMaxDynamicSharedMemorySize, SMEM_GEMM);

    // weight conversions + f_atoms copy
    conv_weight<0><<<(NPAD*KP_BOND + 255)/256, 256>>>(W_i);
    conv_weight<1><<<(NPAD*KP_HID  + 255)/256, 256>>>(W_h);
    conv_weight<2><<<(NPAD*KP_CAT  + 255)/256, 256>>>(W_o);
    copy_atoms<<<(N_ATOMS*ATOM_FDIM + 255)/256, 256>>>(f_atoms);

    const dim3 grid_b(2, (N_BONDS + BM - 1) / BM);
    const dim3 grid_a(2, (N_ATOMS + BM - 1) / BM);

    // 1) inp = f_bonds @ W_i ; msg = relu(inp)
    mma_gemm<0><<<grid_b, 256, SMEM_GEMM>>>(f_bonds, nullptr);

    // 2) message passing x2
    for (int it = 0; it < 2; it++) {
        atom_gather<<<N_ATOMS, 96>>>(a2b);
        bond_prep<<<N_BONDS, 96>>>(b2a, b2revb);
        mma_gemm<1><<<grid_b, 256, SMEM_GEMM>>>(nullptr, nullptr);
    }

    // 3) final gather into concat matrix, readout GEMM
    atom_gather_cat<<<N_ATOMS, 96>>>(a2b);
    mma_gemm<2><<<grid_a, 256, SMEM_GEMM>>>(nullptr, b_o);

    // 4) pool
    pool_kernel<<<N_MOLS_C, 128>>>(a2mol, out);
}